// round 1
// baseline (speedup 1.0000x reference)
#include <cuda_runtime.h>
#include <cstddef>

#define N_SRC   100000
#define N_DST   50000
#define DEG     16
#define NODE_IN 128
#define EDGE_IN 64
#define HID     64

// Scratch: P = node_features @ Wo_top (100000 x 64), R = nf[:50000] @ Wn_top
__device__ float g_P[(size_t)N_SRC * HID];
__device__ float g_R[(size_t)N_DST * HID];

#define PBLOCKS 304
#define RBLOCKS 152

// ---------------------------------------------------------------------------
// Kernel 1: dense projections P and R (first 128 rows of Wo / Wn)
// ---------------------------------------------------------------------------
__global__ __launch_bounds__(256, 2)
void k_proj(const float* __restrict__ nf,
            const float* __restrict__ Wo,
            const float* __restrict__ Wn)
{
    __shared__ float Ws[NODE_IN * HID];   // 32 KB
    __shared__ float nfs[16 * NODE_IN];   // 8 KB

    const int tid = threadIdx.x;
    const bool isP = (blockIdx.x < PBLOCKS);
    const float* W = isP ? Wo : Wn;        // rows 0..127 are the node-feature part
    float* dst = isP ? g_P : g_R;
    const int ntiles  = isP ? (N_SRC / 16) : (N_DST / 16);
    const int tile0   = isP ? blockIdx.x : (blockIdx.x - PBLOCKS);
    const int tstride = isP ? PBLOCKS : RBLOCKS;

    // stage weight (8192 floats = 2048 float4)
    for (int i = tid; i < (NODE_IN * HID) / 4; i += 256)
        ((float4*)Ws)[i] = ((const float4*)W)[i];

    const int s = tid >> 6;   // 0..3 : which group of 4 nodes
    const int h = tid & 63;   // output column

    for (int tile = tile0; tile < ntiles; tile += tstride) {
        __syncthreads();
        const int nbase = tile * 16;
        for (int i = tid; i < (16 * NODE_IN) / 4; i += 256)
            ((float4*)nfs)[i] = ((const float4*)(nf + (size_t)nbase * NODE_IN))[i];
        __syncthreads();

        float acc0 = 0.f, acc1 = 0.f, acc2 = 0.f, acc3 = 0.f;
        #pragma unroll
        for (int q = 0; q < NODE_IN / 4; q++) {
            const float w0 = Ws[(4 * q + 0) * HID + h];
            const float w1 = Ws[(4 * q + 1) * HID + h];
            const float w2 = Ws[(4 * q + 2) * HID + h];
            const float w3 = Ws[(4 * q + 3) * HID + h];
            float4 x;
            x = *(const float4*)&nfs[(0 + s) * NODE_IN + 4 * q];
            acc0 = fmaf(x.x, w0, acc0); acc0 = fmaf(x.y, w1, acc0);
            acc0 = fmaf(x.z, w2, acc0); acc0 = fmaf(x.w, w3, acc0);
            x = *(const float4*)&nfs[(4 + s) * NODE_IN + 4 * q];
            acc1 = fmaf(x.x, w0, acc1); acc1 = fmaf(x.y, w1, acc1);
            acc1 = fmaf(x.z, w2, acc1); acc1 = fmaf(x.w, w3, acc1);
            x = *(const float4*)&nfs[(8 + s) * NODE_IN + 4 * q];
            acc2 = fmaf(x.x, w0, acc2); acc2 = fmaf(x.y, w1, acc2);
            acc2 = fmaf(x.z, w2, acc2); acc2 = fmaf(x.w, w3, acc2);
            x = *(const float4*)&nfs[(12 + s) * NODE_IN + 4 * q];
            acc3 = fmaf(x.x, w0, acc3); acc3 = fmaf(x.y, w1, acc3);
            acc3 = fmaf(x.z, w2, acc3); acc3 = fmaf(x.w, w3, acc3);
        }
        dst[(size_t)(nbase + 0 + s)  * HID + h] = acc0;
        dst[(size_t)(nbase + 4 + s)  * HID + h] = acc1;
        dst[(size_t)(nbase + 8 + s)  * HID + h] = acc2;
        dst[(size_t)(nbase + 12 + s) * HID + h] = acc3;
    }
}

// ---------------------------------------------------------------------------
// Kernel 2: fused per-destination pipeline
//   e_out = relu(edge@We + be); a = leaky(edge.v + c);
//   m = relu(P[src] + e_out@Wo_bot + bo); alpha = sparsemax(a);
//   out = relu(R + (sum_d alpha_d m_d) @ Wn_bot + bn)
// ---------------------------------------------------------------------------

// smem layout (floats)
#define SM_WE    0
#define SM_WOB   4096
#define SM_WNB   8192
#define SM_EDGE  12288          // 4 slots * 16*68
#define SM_EOUT  (12288 + 4352)
#define SM_HN    (SM_EOUT + 4352)      // 4*64
#define SM_V     (SM_HN + 256)         // 64
#define SM_BE    (SM_V + 64)
#define SM_BO    (SM_BE + 64)
#define SM_BN    (SM_BO + 64)
#define SM_A     (SM_BN + 64)          // 4*16
#define SM_SRC   (SM_A + 64)           // 4*16 ints
#define SM_TAU   (SM_SRC + 64)         // 4
#define SM_AMAX  (SM_TAU + 4)          // 4
#define SM_C     (SM_AMAX + 4)         // 4
#define SM_TOTAL ((SM_C + 4) * 4)      // bytes

#define ESTRIDE 1088   // 16 rows * 68 floats (padded)

__global__ __launch_bounds__(256, 2)
void k_fused(const float* __restrict__ ef,
             const int*   __restrict__ src_idx,
             const float* __restrict__ We,  const float* __restrict__ be,
             const float* __restrict__ Wa,  const float* __restrict__ ba,
             const float* __restrict__ wa,
             const float* __restrict__ Wo,  const float* __restrict__ bo,
             const float* __restrict__ Wn,  const float* __restrict__ bn,
             float* __restrict__ out)
{
    extern __shared__ float sm[];
    const int tid = threadIdx.x;

    // one-time staging: weights, biases, collapsed attention vector v, scalar c
    for (int i = tid; i < 1024; i += 256) {
        ((float4*)(sm + SM_WE))[i]  = ((const float4*)We)[i];
        ((float4*)(sm + SM_WOB))[i] = ((const float4*)(Wo + 128 * HID))[i];
        ((float4*)(sm + SM_WNB))[i] = ((const float4*)(Wn + 128 * HID))[i];
    }
    if (tid < 64) {
        sm[SM_BE + tid] = be[tid];
        sm[SM_BO + tid] = bo[tid];
        sm[SM_BN + tid] = bn[tid];
        float sv = 0.f;
        #pragma unroll 8
        for (int k = 0; k < 64; k++) sv = fmaf(Wa[tid * 64 + k], wa[k], sv);
        sm[SM_V + tid] = sv;
    }
    if (tid == 64) {
        float sc = 0.f;
        for (int k = 0; k < 64; k++) sc = fmaf(ba[k], wa[k], sc);
        sm[SM_C] = sc;
    }
    __syncthreads();
    const float cval = sm[SM_C];

    const int slot = tid >> 6;
    const int h    = tid & 63;
    float* es = sm + SM_EDGE + slot * ESTRIDE;
    float* qs = sm + SM_EOUT + slot * ESTRIDE;

    for (int grp = blockIdx.x; grp < N_DST / 4; grp += gridDim.x) {
        const int node = grp * 4 + slot;

        // ---- stage edge tile (16 x 64 floats, padded rows of 68) ----
        const float4* eg = (const float4*)(ef + (size_t)node * (DEG * EDGE_IN));
        #pragma unroll
        for (int t = 0; t < 4; t++) {
            const int j = h + 64 * t;         // 0..255
            const int d = j >> 4, k4 = j & 15;
            *(float4*)&es[d * 68 + 4 * k4] = eg[j];
        }
        if (h < 16) sm[SM_SRC + slot * 16 + h] = __int_as_float(0),
                    ((int*)(sm + SM_SRC))[slot * 16 + h] = src_idx[node * DEG + h];
        __syncthreads();  // S1

        // prefetch P rows (L2-resident) + R row — hidden behind phase 1
        float pld[16];
        #pragma unroll
        for (int d = 0; d < 16; d++) {
            const int sidx = ((const int*)(sm + SM_SRC))[slot * 16 + d];
            pld[d] = g_P[(size_t)sidx * HID + h];
        }
        const float rld = g_R[(size_t)node * HID + h];

        // ---- attention logits (threads 0..15 of slot) ----
        if (h < 16) {
            float sa = cval;
            #pragma unroll
            for (int k = 0; k < 64; k++) sa = fmaf(es[h * 68 + k], sm[SM_V + k], sa);
            sm[SM_A + slot * 16 + h] = (sa > 0.f) ? sa : 0.01f * sa;  // leaky_relu
        }

        // ---- phase 1: e_out[d][h] = relu(edge @ We + be) ----
        float acc[16];
        const float bev = sm[SM_BE + h];
        #pragma unroll
        for (int d = 0; d < 16; d++) acc[d] = bev;
        #pragma unroll
        for (int q = 0; q < 16; q++) {
            const float w0 = sm[SM_WE + (4 * q + 0) * 64 + h];
            const float w1 = sm[SM_WE + (4 * q + 1) * 64 + h];
            const float w2 = sm[SM_WE + (4 * q + 2) * 64 + h];
            const float w3 = sm[SM_WE + (4 * q + 3) * 64 + h];
            #pragma unroll
            for (int d = 0; d < 16; d++) {
                const float4 x = *(const float4*)&es[d * 68 + 4 * q];
                acc[d] = fmaf(x.x, w0, acc[d]); acc[d] = fmaf(x.y, w1, acc[d]);
                acc[d] = fmaf(x.z, w2, acc[d]); acc[d] = fmaf(x.w, w3, acc[d]);
            }
        }
        #pragma unroll
        for (int d = 0; d < 16; d++) qs[d * 68 + h] = fmaxf(acc[d], 0.f);
        __syncthreads();  // S2: a_s + eout ready

        // ---- sparsemax (1 thread per slot), overlapped with phase 2 ----
        if (h == 0) {
            float z[16];
            float amax = -3.4e38f;
            #pragma unroll
            for (int d = 0; d < 16; d++) { z[d] = sm[SM_A + slot * 16 + d]; amax = fmaxf(amax, z[d]); }
            #pragma unroll
            for (int d = 0; d < 16; d++) z[d] -= amax;
            // bitonic sort ascending (fully unrolled -> registers)
            #pragma unroll
            for (int k = 2; k <= 16; k <<= 1) {
                #pragma unroll
                for (int j = k >> 1; j > 0; j >>= 1) {
                    #pragma unroll
                    for (int i = 0; i < 16; i++) {
                        const int l = i ^ j;
                        if (l > i) {
                            const bool up = ((i & k) == 0);
                            const float a0 = z[i], b0 = z[l];
                            const bool sw = up ? (a0 > b0) : (a0 < b0);
                            if (sw) { z[i] = b0; z[l] = a0; }
                        }
                    }
                }
            }
            // descending view: zs[j-1] = z[16-j]
            float cs = 0.f, cssel = 0.f, kk = 1.f;
            #pragma unroll
            for (int j = 1; j <= 16; j++) {
                const float zz = z[16 - j];
                cs += zz;
                if (1.f + (float)j * zz > cs) { kk = (float)j; cssel = cs; }
            }
            sm[SM_TAU + slot]  = (cssel - 1.f) / kk;
            sm[SM_AMAX + slot] = amax;
        }

        // ---- phase 2: m[d][h] = relu(P[src] + e_out @ Wo_bot + bo) ----
        const float bov = sm[SM_BO + h];
        #pragma unroll
        for (int d = 0; d < 16; d++) acc[d] = pld[d] + bov;
        #pragma unroll
        for (int q = 0; q < 16; q++) {
            const float w0 = sm[SM_WOB + (4 * q + 0) * 64 + h];
            const float w1 = sm[SM_WOB + (4 * q + 1) * 64 + h];
            const float w2 = sm[SM_WOB + (4 * q + 2) * 64 + h];
            const float w3 = sm[SM_WOB + (4 * q + 3) * 64 + h];
            #pragma unroll
            for (int d = 0; d < 16; d++) {
                const float4 x = *(const float4*)&qs[d * 68 + 4 * q];
                acc[d] = fmaf(x.x, w0, acc[d]); acc[d] = fmaf(x.y, w1, acc[d]);
                acc[d] = fmaf(x.z, w2, acc[d]); acc[d] = fmaf(x.w, w3, acc[d]);
            }
        }
        #pragma unroll
        for (int d = 0; d < 16; d++) acc[d] = fmaxf(acc[d], 0.f);
        __syncthreads();  // S3: tau visible

        // ---- weighted aggregation (m stays in registers) ----
        const float amax = sm[SM_AMAX + slot];
        const float tau  = sm[SM_TAU + slot];
        float hn = 0.f;
        #pragma unroll
        for (int d = 0; d < 16; d++) {
            const float al = fmaxf(sm[SM_A + slot * 16 + d] - amax - tau, 0.f);
            hn = fmaf(al, acc[d], hn);
        }
        sm[SM_HN + slot * 64 + h] = hn;
        __syncthreads();  // S4

        // ---- phase 3: out = relu(R + h_neigh @ Wn_bot + bn) ----
        float o = 0.f;
        #pragma unroll
        for (int q = 0; q < 16; q++) {
            const float4 x = *(const float4*)&sm[SM_HN + slot * 64 + 4 * q];
            const float w0 = sm[SM_WNB + (4 * q + 0) * 64 + h];
            const float w1 = sm[SM_WNB + (4 * q + 1) * 64 + h];
            const float w2 = sm[SM_WNB + (4 * q + 2) * 64 + h];
            const float w3 = sm[SM_WNB + (4 * q + 3) * 64 + h];
            o = fmaf(x.x, w0, o); o = fmaf(x.y, w1, o);
            o = fmaf(x.z, w2, o); o = fmaf(x.w, w3, o);
        }
        o += rld + sm[SM_BN + h];
        out[(size_t)node * HID + h] = fmaxf(o, 0.f);
        // next-iteration S1 provides the rendezvous before smem reuse
    }
}

// ---------------------------------------------------------------------------
extern "C" void kernel_launch(void* const* d_in, const int* in_sizes, int n_in,
                              void* d_out, int out_size)
{
    const float* nf = (const float*)d_in[0];
    const float* ef = (const float*)d_in[1];
    const int*   si = (const int*)  d_in[2];
    const float* We = (const float*)d_in[3];
    const float* be = (const float*)d_in[4];
    const float* Wa = (const float*)d_in[5];
    const float* ba = (const float*)d_in[6];
    const float* wa = (const float*)d_in[7];
    const float* Wo = (const float*)d_in[8];
    const float* bo = (const float*)d_in[9];
    const float* Wn = (const float*)d_in[10];
    const float* bn = (const float*)d_in[11];
    float* out = (float*)d_out;

    cudaFuncSetAttribute(k_fused, cudaFuncAttributeMaxDynamicSharedMemorySize, SM_TOTAL);

    k_proj<<<PBLOCKS + RBLOCKS, 256>>>(nf, Wo, Wn);
    k_fused<<<304, 256, SM_TOTAL>>>(ef, si, We, be, Wa, ba, wa, Wo, bo, Wn, bn, out);
}

// round 3
// speedup vs baseline: 2.4777x; 2.4777x over previous
#include <cuda_runtime.h>
#include <cuda_bf16.h>
#include <cstdint>
#include <cstddef>

#define N_SRC   100000
#define N_DST   50000
#define DEG     16
#define NODE_IN 128
#define HID     64

__device__ float g_P[(size_t)N_SRC * HID];
__device__ float g_R[(size_t)N_DST * HID];

// ---------------------------------------------------------------------------
// mma.sync / ldmatrix helpers (sm_80+ ISA, valid on non-'a' sm_103 target)
// ---------------------------------------------------------------------------
__device__ __forceinline__ uint32_t smem_u32(const void* p) {
    uint32_t a;
    asm("{ .reg .u64 t; cvta.to.shared.u64 t, %1; cvt.u32.u64 %0, t; }" : "=r"(a) : "l"(p));
    return a;
}
__device__ __forceinline__ void ldsm4(uint32_t r[4], uint32_t addr) {
    asm volatile("ldmatrix.sync.aligned.m8n8.x4.shared.b16 {%0,%1,%2,%3}, [%4];"
        : "=r"(r[0]), "=r"(r[1]), "=r"(r[2]), "=r"(r[3]) : "r"(addr));
}
__device__ __forceinline__ void mma_bf16(float d[4], const uint32_t a[4],
                                         uint32_t b0, uint32_t b1) {
    asm volatile("mma.sync.aligned.m16n8k16.row.col.f32.bf16.bf16.f32 "
        "{%0,%1,%2,%3}, {%4,%5,%6,%7}, {%8,%9}, {%0,%1,%2,%3};"
        : "+f"(d[0]), "+f"(d[1]), "+f"(d[2]), "+f"(d[3])
        : "r"(a[0]), "r"(a[1]), "r"(a[2]), "r"(a[3]), "r"(b0), "r"(b1));
}

// 3-pass bf16-split GEMM: D(128x64) += A(128xK) @ B^T(64xK), warp tile 32x32.
// A,B in smem as hi/lo bf16 tiles, row stride = STRIDE elements (pad keeps
// LDSM conflict-free: STRIDE*2 bytes ≡ 16 mod 128).
template<int KSTEPS, int STRIDE>
__device__ __forceinline__ void gemm_x3(uint32_t aH, uint32_t aL,
                                        uint32_t bH, uint32_t bL,
                                        int mrow, int ncol, int lane,
                                        float acc[2][4][4]) {
    const int arow = mrow + (lane & 15);
    const int asel = (lane >> 4) * 8;
    const int brow = ncol + ((lane >> 4) << 3) + (lane & 7);
    const int bsel = ((lane >> 3) & 1) * 8;
    #pragma unroll
    for (int ks = 0; ks < KSTEPS; ks++) {
        uint32_t ah[2][4], al[2][4], bh[2][4], bl[2][4];
        #pragma unroll
        for (int mt = 0; mt < 2; mt++) {
            const uint32_t off = (uint32_t)(((arow + mt * 16) * STRIDE + ks * 16 + asel) * 2);
            ldsm4(ah[mt], aH + off);
            ldsm4(al[mt], aL + off);
        }
        #pragma unroll
        for (int j = 0; j < 2; j++) {
            const uint32_t off = (uint32_t)(((brow + j * 16) * STRIDE + ks * 16 + bsel) * 2);
            ldsm4(bh[j], bH + off);
            ldsm4(bl[j], bL + off);
        }
        #pragma unroll
        for (int mt = 0; mt < 2; mt++)
            #pragma unroll
            for (int nt = 0; nt < 4; nt++) {
                const int j = nt >> 1, hf = (nt & 1) * 2;
                mma_bf16(acc[mt][nt], ah[mt], bh[j][hf], bh[j][hf + 1]);
                mma_bf16(acc[mt][nt], ah[mt], bl[j][hf], bl[j][hf + 1]);
                mma_bf16(acc[mt][nt], al[mt], bh[j][hf], bh[j][hf + 1]);
            }
    }
}

__device__ __forceinline__ void split2(float a, float b,
                                       __nv_bfloat162& h, __nv_bfloat162& l) {
    h = __floats2bfloat162_rn(a, b);
    const float2 f = __bfloat1622float2(h);
    l = __floats2bfloat162_rn(a - f.x, b - f.y);
}

// ---------------------------------------------------------------------------
// Kernel 1: P = nf @ Wo_top, R = nf[:N_DST] @ Wn_top  (M-tiles of 128, K=128)
// ---------------------------------------------------------------------------
#define POFF_AH 0
#define POFF_AL 34816
#define POFF_WH 69632
#define POFF_WL 87040
#define PJ_SMEM 104448
#define PJ_BLOCKS 296
#define PJ_PSPLIT 197

__global__ __launch_bounds__(256, 2)
void k_projT(const float* __restrict__ nf,
             const float* __restrict__ Wo,
             const float* __restrict__ Wn)
{
    extern __shared__ char smc[];
    const int tid = threadIdx.x, lane = tid & 31, wid = tid >> 5;
    const int mrow = (wid & 3) * 32, ncol = (wid >> 2) * 32;

    const bool isP = (blockIdx.x < PJ_PSPLIT);
    const float* W = isP ? Wo : Wn;
    float* dst = isP ? g_P : g_R;
    const int limit = isP ? N_SRC : N_DST;
    const int ntile = (limit + 127) >> 7;
    const int t0 = isP ? blockIdx.x : (blockIdx.x - PJ_PSPLIT);
    const int ts = isP ? PJ_PSPLIT : (PJ_BLOCKS - PJ_PSPLIT);

    // stage transposed weight hi/lo: [n=64][k=128], stride 136
    for (int i = tid; i < 64 * 128; i += 256) {
        const int n = i >> 7, k = i & 127;
        const float w = W[k * 64 + n];
        const __nv_bfloat16 h = __float2bfloat16(w);
        ((__nv_bfloat16*)(smc + POFF_WH))[n * 136 + k] = h;
        ((__nv_bfloat16*)(smc + POFF_WL))[n * 136 + k] =
            __float2bfloat16(w - __bfloat162float(h));
    }
    const uint32_t aH = smem_u32(smc + POFF_AH), aL = smem_u32(smc + POFF_AL);
    const uint32_t bH = smem_u32(smc + POFF_WH), bL = smem_u32(smc + POFF_WL);

    for (int tile = t0; tile < ntile; tile += ts) {
        __syncthreads();
        const int base = tile * 128;
        #pragma unroll
        for (int t = 0; t < 16; t++) {
            const int idx = tid + 256 * t;          // 0..4095 float4s
            const int r = idx >> 5, q = idx & 31;
            float4 v = make_float4(0.f, 0.f, 0.f, 0.f);
            if (base + r < limit)
                v = ((const float4*)(nf + (size_t)(base + r) * NODE_IN))[q];
            __nv_bfloat162 h0, l0, h1, l1;
            split2(v.x, v.y, h0, l0);
            split2(v.z, v.w, h1, l1);
            char* ph = smc + POFF_AH + (size_t)(r * 136 + 4 * q) * 2;
            char* pl = smc + POFF_AL + (size_t)(r * 136 + 4 * q) * 2;
            *(__nv_bfloat162*)ph = h0; *(__nv_bfloat162*)(ph + 4) = h1;
            *(__nv_bfloat162*)pl = l0; *(__nv_bfloat162*)(pl + 4) = l1;
        }
        __syncthreads();

        float acc[2][4][4];
        #pragma unroll
        for (int a = 0; a < 2; a++)
            #pragma unroll
            for (int b = 0; b < 4; b++)
                #pragma unroll
                for (int c = 0; c < 4; c++) acc[a][b][c] = 0.f;

        gemm_x3<8, 136>(aH, aL, bH, bL, mrow, ncol, lane, acc);

        #pragma unroll
        for (int mt = 0; mt < 2; mt++) {
            const int r0 = base + mrow + mt * 16 + (lane >> 2);
            #pragma unroll
            for (int nt = 0; nt < 4; nt++) {
                const int c = ncol + nt * 8 + (lane & 3) * 2;
                if (r0 < limit)
                    *(float2*)(dst + (size_t)r0 * HID + c) =
                        make_float2(acc[mt][nt][0], acc[mt][nt][1]);
                if (r0 + 8 < limit)
                    *(float2*)(dst + (size_t)(r0 + 8) * HID + c) =
                        make_float2(acc[mt][nt][2], acc[mt][nt][3]);
            }
        }
    }
}

// ---------------------------------------------------------------------------
// Kernel 2: fused per-destination pipeline (8 nodes / 128 edges per tile)
// ---------------------------------------------------------------------------
#define OFF_EH  0
#define OFF_EL  18432
#define OFF_W1H 36864
#define OFF_W1L 46080
#define OFF_W2H 55296
#define OFF_W2L 64512
#define OFF_WN  73728
#define OFF_HN  90112
#define OFF_LOG 92160
#define OFF_TAU 92672
#define OFF_AMX 92704
#define OFF_V   92736
#define OFF_BE  92992
#define OFF_BO  93248
#define OFF_BN  93504
#define OFF_SRC 93760
#define OFF_C   94272
#define FS_SMEM 94336
#define NTILE   (N_DST / 8)

__global__ __launch_bounds__(256, 2)
void k_fusedT(const float* __restrict__ ef,
              const int*   __restrict__ src_idx,
              const float* __restrict__ We,  const float* __restrict__ be,
              const float* __restrict__ Wa,  const float* __restrict__ ba,
              const float* __restrict__ wa,
              const float* __restrict__ Wo,  const float* __restrict__ bo,
              const float* __restrict__ Wn,  const float* __restrict__ bn,
              float* __restrict__ out)
{
    extern __shared__ char smc[];
    const int tid = threadIdx.x, lane = tid & 31, wid = tid >> 5;
    const int mrow = (wid & 3) * 32, ncol = (wid >> 2) * 32;

    float* sWN  = (float*)(smc + OFF_WN);
    float* sHN  = (float*)(smc + OFF_HN);
    float* sLog = (float*)(smc + OFF_LOG);
    float* sTau = (float*)(smc + OFF_TAU);
    float* sAmx = (float*)(smc + OFF_AMX);
    float* sV   = (float*)(smc + OFF_V);
    float* sBe  = (float*)(smc + OFF_BE);
    float* sBo  = (float*)(smc + OFF_BO);
    float* sBn  = (float*)(smc + OFF_BN);
    int*   sSrc = (int*)  (smc + OFF_SRC);

    // one-time staging
    for (int i = tid; i < 4096; i += 256) {
        const int n = i >> 6, k = i & 63;
        const float w1 = We[k * 64 + n];
        const float w2 = Wo[(NODE_IN + k) * 64 + n];
        __nv_bfloat16 h1 = __float2bfloat16(w1);
        __nv_bfloat16 h2 = __float2bfloat16(w2);
        ((__nv_bfloat16*)(smc + OFF_W1H))[n * 72 + k] = h1;
        ((__nv_bfloat16*)(smc + OFF_W1L))[n * 72 + k] = __float2bfloat16(w1 - __bfloat162float(h1));
        ((__nv_bfloat16*)(smc + OFF_W2H))[n * 72 + k] = h2;
        ((__nv_bfloat16*)(smc + OFF_W2L))[n * 72 + k] = __float2bfloat16(w2 - __bfloat162float(h2));
    }
    for (int i = tid; i < 1024; i += 256)
        ((float4*)sWN)[i] = ((const float4*)(Wn + NODE_IN * 64))[i];
    if (tid < 64) {
        sBe[tid] = be[tid]; sBo[tid] = bo[tid]; sBn[tid] = bn[tid];
        float sv = 0.f;
        #pragma unroll 8
        for (int k = 0; k < 64; k++) sv = fmaf(Wa[tid * 64 + k], wa[k], sv);
        sV[tid] = sv;
    }
    if (tid == 64) {
        float sc = 0.f;
        for (int k = 0; k < 64; k++) sc = fmaf(ba[k], wa[k], sc);
        *(float*)(smc + OFF_C) = sc;
    }
    __syncthreads();
    const float cval = *(const float*)(smc + OFF_C);

    const uint32_t eH = smem_u32(smc + OFF_EH),  eL = smem_u32(smc + OFF_EL);
    const uint32_t w1H = smem_u32(smc + OFF_W1H), w1L = smem_u32(smc + OFF_W1L);
    const uint32_t w2H = smem_u32(smc + OFF_W2H), w2L = smem_u32(smc + OFF_W2L);

    for (int tile = blockIdx.x; tile < NTILE; tile += gridDim.x) {
        __syncthreads();   // reuse guard

        // ---- stage E tile [128 x 64] -> hi/lo bf16, stride 72 ----
        const float4* eg = (const float4*)(ef + (size_t)tile * 8192);
        #pragma unroll
        for (int t = 0; t < 8; t++) {
            const int idx = tid + 256 * t;       // 0..2047
            const int r = idx >> 4, q = idx & 15;
            const float4 v = eg[idx];
            __nv_bfloat162 h0, l0, h1, l1;
            split2(v.x, v.y, h0, l0);
            split2(v.z, v.w, h1, l1);
            char* ph = smc + OFF_EH + (size_t)(r * 72 + 4 * q) * 2;
            char* pl = smc + OFF_EL + (size_t)(r * 72 + 4 * q) * 2;
            *(__nv_bfloat162*)ph = h0; *(__nv_bfloat162*)(ph + 4) = h1;
            *(__nv_bfloat162*)pl = l0; *(__nv_bfloat162*)(pl + 4) = l1;
        }
        if (tid < 128) sSrc[tid] = src_idx[tile * 128 + tid];
        __syncthreads();

        // ---- attention logits ----
        if (tid < 128) {
            const __nv_bfloat162* ph = (const __nv_bfloat162*)(smc + OFF_EH + (size_t)tid * 144);
            const __nv_bfloat162* pl = (const __nv_bfloat162*)(smc + OFF_EL + (size_t)tid * 144);
            float a = cval;
            #pragma unroll 8
            for (int q = 0; q < 32; q++) {
                const float2 h2 = __bfloat1622float2(ph[q]);
                const float2 l2 = __bfloat1622float2(pl[q]);
                a = fmaf(h2.x + l2.x, sV[2 * q], a);
                a = fmaf(h2.y + l2.y, sV[2 * q + 1], a);
            }
            sLog[tid] = (a > 0.f) ? a : 0.01f * a;
        }
        __syncthreads();

        // ---- sparsemax (register bitonic, 1 thread per node) ----
        if (tid < 8) {
            float z[16], amax = -3.4e38f;
            #pragma unroll
            for (int d = 0; d < 16; d++) { z[d] = sLog[tid * 16 + d]; amax = fmaxf(amax, z[d]); }
            #pragma unroll
            for (int d = 0; d < 16; d++) z[d] -= amax;
            #pragma unroll
            for (int kk2 = 2; kk2 <= 16; kk2 <<= 1)
                #pragma unroll
                for (int j = kk2 >> 1; j > 0; j >>= 1)
                    #pragma unroll
                    for (int i = 0; i < 16; i++) {
                        const int l = i ^ j;
                        if (l > i) {
                            const bool up = ((i & kk2) == 0);
                            const float a0 = z[i], b0 = z[l];
                            if (up ? (a0 > b0) : (a0 < b0)) { z[i] = b0; z[l] = a0; }
                        }
                    }
            float cs = 0.f, cssel = 0.f, kk = 1.f;
            #pragma unroll
            for (int j = 1; j <= 16; j++) {
                const float zz = z[16 - j];
                cs += zz;
                if (1.f + (float)j * zz > cs) { kk = (float)j; cssel = cs; }
            }
            sTau[tid] = (cssel - 1.f) / kk;
            sAmx[tid] = amax;
        }

        float acc[2][4][4];

        // ---- GEMM1: e_out_pre = E @ We^T ----
        #pragma unroll
        for (int a = 0; a < 2; a++)
            #pragma unroll
            for (int b = 0; b < 4; b++)
                #pragma unroll
                for (int c = 0; c < 4; c++) acc[a][b][c] = 0.f;
        gemm_x3<4, 72>(eH, eL, w1H, w1L, mrow, ncol, lane, acc);
        __syncthreads();   // all E reads complete (e_out aliases E)

        // ---- epilogue1: relu(+be) -> bf16 hi/lo back into E buffers ----
        #pragma unroll
        for (int mt = 0; mt < 2; mt++) {
            const int r0 = mrow + mt * 16 + (lane >> 2);
            #pragma unroll
            for (int nt = 0; nt < 4; nt++) {
                const int c = ncol + nt * 8 + (lane & 3) * 2;
                const float x0 = fmaxf(acc[mt][nt][0] + sBe[c],     0.f);
                const float x1 = fmaxf(acc[mt][nt][1] + sBe[c + 1], 0.f);
                const float x2 = fmaxf(acc[mt][nt][2] + sBe[c],     0.f);
                const float x3 = fmaxf(acc[mt][nt][3] + sBe[c + 1], 0.f);
                __nv_bfloat162 h0, l0, h1, l1;
                split2(x0, x1, h0, l0);
                split2(x2, x3, h1, l1);
                *(__nv_bfloat162*)(smc + OFF_EH + (size_t)(r0 * 72 + c) * 2) = h0;
                *(__nv_bfloat162*)(smc + OFF_EL + (size_t)(r0 * 72 + c) * 2) = l0;
                *(__nv_bfloat162*)(smc + OFF_EH + (size_t)((r0 + 8) * 72 + c) * 2) = h1;
                *(__nv_bfloat162*)(smc + OFF_EL + (size_t)((r0 + 8) * 72 + c) * 2) = l1;
            }
        }
        __syncthreads();

        // ---- GEMM2: m_pre = e_out @ Wo_bot^T ----
        #pragma unroll
        for (int a = 0; a < 2; a++)
            #pragma unroll
            for (int b = 0; b < 4; b++)
                #pragma unroll
                for (int c = 0; c < 4; c++) acc[a][b][c] = 0.f;
        gemm_x3<4, 72>(eH, eL, w2H, w2L, mrow, ncol, lane, acc);

        // ---- epilogue2: m = relu(m_pre + P[src] + bo); alpha-weighted sum ----
        #pragma unroll
        for (int mt = 0; mt < 2; mt++) {
            const int ln = (mrow >> 4) + mt;               // local node 0..7
            const int r0 = mrow + mt * 16 + (lane >> 2);
            const int r1 = r0 + 8;
            const int s0 = sSrc[r0], s1 = sSrc[r1];
            const float al0 = fmaxf(sLog[r0] - sAmx[ln] - sTau[ln], 0.f);
            const float al1 = fmaxf(sLog[r1] - sAmx[ln] - sTau[ln], 0.f);
            #pragma unroll
            for (int nt = 0; nt < 4; nt++) {
                const int c = ncol + nt * 8 + (lane & 3) * 2;
                const float2 p0 = *(const float2*)(g_P + (size_t)s0 * HID + c);
                const float2 p1 = *(const float2*)(g_P + (size_t)s1 * HID + c);
                const float m00 = fmaxf(acc[mt][nt][0] + p0.x + sBo[c],     0.f);
                const float m01 = fmaxf(acc[mt][nt][1] + p0.y + sBo[c + 1], 0.f);
                const float m10 = fmaxf(acc[mt][nt][2] + p1.x + sBo[c],     0.f);
                const float m11 = fmaxf(acc[mt][nt][3] + p1.y + sBo[c + 1], 0.f);
                float sx = m00 * al0 + m10 * al1;
                float sy = m01 * al0 + m11 * al1;
                sx += __shfl_xor_sync(0xffffffffu, sx, 4);
                sy += __shfl_xor_sync(0xffffffffu, sy, 4);
                sx += __shfl_xor_sync(0xffffffffu, sx, 8);
                sy += __shfl_xor_sync(0xffffffffu, sy, 8);
                sx += __shfl_xor_sync(0xffffffffu, sx, 16);
                sy += __shfl_xor_sync(0xffffffffu, sy, 16);
                if (lane < 4) *(float2*)(sHN + ln * 64 + c) = make_float2(sx, sy);
            }
        }
        __syncthreads();

        // ---- GEMM3 (scalar): out = relu(R + h_neigh @ Wn_bot + bn) ----
        #pragma unroll
        for (int t = 0; t < 2; t++) {
            const int idx = tid + 256 * t;
            const int ln = idx >> 6, h = idx & 63;
            const int node = tile * 8 + ln;
            float o = sBn[h];
            #pragma unroll 16
            for (int k = 0; k < 64; k++)
                o = fmaf(sHN[ln * 64 + k], sWN[k * 64 + h], o);
            o += g_R[(size_t)node * HID + h];
            out[(size_t)node * HID + h] = fmaxf(o, 0.f);
        }
    }
}

// ---------------------------------------------------------------------------
extern "C" void kernel_launch(void* const* d_in, const int* in_sizes, int n_in,
                              void* d_out, int out_size)
{
    const float* nf = (const float*)d_in[0];
    const float* ef = (const float*)d_in[1];
    const int*   si = (const int*)  d_in[2];
    const float* We = (const float*)d_in[3];
    const float* be = (const float*)d_in[4];
    const float* Wa = (const float*)d_in[5];
    const float* ba = (const float*)d_in[6];
    const float* wa = (const float*)d_in[7];
    const float* Wo = (const float*)d_in[8];
    const float* bo = (const float*)d_in[9];
    const float* Wn = (const float*)d_in[10];
    const float* bn = (const float*)d_in[11];
    float* out = (float*)d_out;

    cudaFuncSetAttribute(k_projT,  cudaFuncAttributeMaxDynamicSharedMemorySize, PJ_SMEM);
    cudaFuncSetAttribute(k_fusedT, cudaFuncAttributeMaxDynamicSharedMemorySize, FS_SMEM);

    k_projT<<<PJ_BLOCKS, 256, PJ_SMEM>>>(nf, Wo, Wn);
    k_fusedT<<<296, 256, FS_SMEM>>>(ef, si, We, be, Wa, ba, wa, Wo, bo, Wn, bn, out);
}

// round 4
// speedup vs baseline: 2.9073x; 1.1734x over previous
#include <cuda_runtime.h>
#include <cuda_bf16.h>
#include <cstdint>
#include <cstddef>

#define N_SRC   100000
#define N_DST   50000
#define DEG     16
#define NODE_IN 128
#define HID     64

__device__ float g_P[(size_t)N_SRC * HID];
__device__ float g_R[(size_t)N_DST * HID];

// ---------------------------------------------------------------------------
// mma.sync / ldmatrix helpers (sm_80+ ISA, valid on non-'a' sm_103 target)
// ---------------------------------------------------------------------------
__device__ __forceinline__ uint32_t smem_u32(const void* p) {
    uint32_t a;
    asm("{ .reg .u64 t; cvta.to.shared.u64 t, %1; cvt.u32.u64 %0, t; }" : "=r"(a) : "l"(p));
    return a;
}
__device__ __forceinline__ void ldsm4(uint32_t r[4], uint32_t addr) {
    asm volatile("ldmatrix.sync.aligned.m8n8.x4.shared.b16 {%0,%1,%2,%3}, [%4];"
        : "=r"(r[0]), "=r"(r[1]), "=r"(r[2]), "=r"(r[3]) : "r"(addr));
}
__device__ __forceinline__ void mma_bf16(float d[4], const uint32_t a[4],
                                         uint32_t b0, uint32_t b1) {
    asm volatile("mma.sync.aligned.m16n8k16.row.col.f32.bf16.bf16.f32 "
        "{%0,%1,%2,%3}, {%4,%5,%6,%7}, {%8,%9}, {%0,%1,%2,%3};"
        : "+f"(d[0]), "+f"(d[1]), "+f"(d[2]), "+f"(d[3])
        : "r"(a[0]), "r"(a[1]), "r"(a[2]), "r"(a[3]), "r"(b0), "r"(b1));
}

// 3-pass bf16-split GEMM: D(128x64) += A(128xK) @ B^T(64xK), warp tile 32x32.
template<int KSTEPS, int STRIDE>
__device__ __forceinline__ void gemm_x3(uint32_t aH, uint32_t aL,
                                        uint32_t bH, uint32_t bL,
                                        int mrow, int ncol, int lane,
                                        float acc[2][4][4]) {
    const int arow = mrow + (lane & 15);
    const int asel = (lane >> 4) * 8;
    const int brow = ncol + ((lane >> 4) << 3) + (lane & 7);
    const int bsel = ((lane >> 3) & 1) * 8;
    #pragma unroll
    for (int ks = 0; ks < KSTEPS; ks++) {
        uint32_t ah[2][4], al[2][4], bh[2][4], bl[2][4];
        #pragma unroll
        for (int mt = 0; mt < 2; mt++) {
            const uint32_t off = (uint32_t)(((arow + mt * 16) * STRIDE + ks * 16 + asel) * 2);
            ldsm4(ah[mt], aH + off);
            ldsm4(al[mt], aL + off);
        }
        #pragma unroll
        for (int j = 0; j < 2; j++) {
            const uint32_t off = (uint32_t)(((brow + j * 16) * STRIDE + ks * 16 + bsel) * 2);
            ldsm4(bh[j], bH + off);
            ldsm4(bl[j], bL + off);
        }
        #pragma unroll
        for (int mt = 0; mt < 2; mt++)
            #pragma unroll
            for (int nt = 0; nt < 4; nt++) {
                const int j = nt >> 1, hf = (nt & 1) * 2;
                mma_bf16(acc[mt][nt], ah[mt], bh[j][hf], bh[j][hf + 1]);
                mma_bf16(acc[mt][nt], ah[mt], bl[j][hf], bl[j][hf + 1]);
                mma_bf16(acc[mt][nt], al[mt], bh[j][hf], bh[j][hf + 1]);
            }
    }
}

__device__ __forceinline__ void split2(float a, float b,
                                       __nv_bfloat162& h, __nv_bfloat162& l) {
    h = __floats2bfloat162_rn(a, b);
    const float2 f = __bfloat1622float2(h);
    l = __floats2bfloat162_rn(a - f.x, b - f.y);
}
__device__ __forceinline__ uint32_t b2u(__nv_bfloat162 v) {
    return *(uint32_t*)&v;
}

// ---------------------------------------------------------------------------
// Kernel 1: P = nf @ Wo_top, R = nf[:N_DST] @ Wn_top  (M-tiles of 128, K=128)
// ---------------------------------------------------------------------------
#define POFF_AH 0
#define POFF_AL 34816
#define POFF_WH 69632
#define POFF_WL 87040
#define PJ_SMEM 104448
#define PJ_BLOCKS 296
#define PJ_PSPLIT 197

__global__ __launch_bounds__(256, 2)
void k_projT(const float* __restrict__ nf,
             const float* __restrict__ Wo,
             const float* __restrict__ Wn)
{
    extern __shared__ char smc[];
    const int tid = threadIdx.x, lane = tid & 31, wid = tid >> 5;
    const int mrow = (wid & 3) * 32, ncol = (wid >> 2) * 32;

    const bool isP = (blockIdx.x < PJ_PSPLIT);
    const float* W = isP ? Wo : Wn;
    float* dst = isP ? g_P : g_R;
    const int limit = isP ? N_SRC : N_DST;
    const int ntile = (limit + 127) >> 7;
    const int t0 = isP ? blockIdx.x : (blockIdx.x - PJ_PSPLIT);
    const int ts = isP ? PJ_PSPLIT : (PJ_BLOCKS - PJ_PSPLIT);

    // stage transposed weight hi/lo: [n=64][k=128], stride 136
    for (int i = tid; i < 64 * 128; i += 256) {
        const int n = i >> 7, k = i & 127;
        const float w = W[k * 64 + n];
        const __nv_bfloat16 h = __float2bfloat16(w);
        ((__nv_bfloat16*)(smc + POFF_WH))[n * 136 + k] = h;
        ((__nv_bfloat16*)(smc + POFF_WL))[n * 136 + k] =
            __float2bfloat16(w - __bfloat162float(h));
    }
    const uint32_t aH = smem_u32(smc + POFF_AH), aL = smem_u32(smc + POFF_AL);
    const uint32_t bH = smem_u32(smc + POFF_WH), bL = smem_u32(smc + POFF_WL);

    for (int tile = t0; tile < ntile; tile += ts) {
        __syncthreads();
        const int base = tile * 128;
        #pragma unroll
        for (int t = 0; t < 16; t++) {
            const int idx = tid + 256 * t;          // 0..4095 float4s
            const int r = idx >> 5, q = idx & 31;
            float4 v = make_float4(0.f, 0.f, 0.f, 0.f);
            if (base + r < limit)
                v = ((const float4*)(nf + (size_t)(base + r) * NODE_IN))[q];
            __nv_bfloat162 h0, l0, h1, l1;
            split2(v.x, v.y, h0, l0);
            split2(v.z, v.w, h1, l1);
            const size_t bo_ = (size_t)(r * 136 + 4 * q) * 2;
            *(uint2*)(smc + POFF_AH + bo_) = make_uint2(b2u(h0), b2u(h1));
            *(uint2*)(smc + POFF_AL + bo_) = make_uint2(b2u(l0), b2u(l1));
        }
        __syncthreads();

        float acc[2][4][4];
        #pragma unroll
        for (int a = 0; a < 2; a++)
            #pragma unroll
            for (int b = 0; b < 4; b++)
                #pragma unroll
                for (int c = 0; c < 4; c++) acc[a][b][c] = 0.f;

        gemm_x3<8, 136>(aH, aL, bH, bL, mrow, ncol, lane, acc);

        #pragma unroll
        for (int mt = 0; mt < 2; mt++) {
            const int r0 = base + mrow + mt * 16 + (lane >> 2);
            #pragma unroll
            for (int nt = 0; nt < 4; nt++) {
                const int c = ncol + nt * 8 + (lane & 3) * 2;
                if (r0 < limit)
                    *(float2*)(dst + (size_t)r0 * HID + c) =
                        make_float2(acc[mt][nt][0], acc[mt][nt][1]);
                if (r0 + 8 < limit)
                    *(float2*)(dst + (size_t)(r0 + 8) * HID + c) =
                        make_float2(acc[mt][nt][2], acc[mt][nt][3]);
            }
        }
    }
}

// ---------------------------------------------------------------------------
// Kernel 2: fused per-destination pipeline (8 nodes / 128 edges per tile)
// ---------------------------------------------------------------------------
#define OFF_EH   0
#define OFF_EL   18432
#define OFF_W1H  36864
#define OFF_W1L  46080
#define OFF_W2H  55296
#define OFF_W2L  64512
#define OFF_W3H  73728
#define OFF_W3L  82944
#define OFF_HNH  92160   // 16 x 72 bf16 (rows 8..15 stay zero)
#define OFF_HNL  94464
#define OFF_LOG  96768   // 128 floats
#define OFF_TAU  97280
#define OFF_AMX  97312
#define OFF_V    97344
#define OFF_BE   97600
#define OFF_BO   97856
#define OFF_BN   98112
#define OFF_SRC  98368
#define OFF_C    98880
#define FS_SMEM  98944
#define NTILE    (N_DST / 8)

__global__ __launch_bounds__(256, 2)
void k_fusedT(const float* __restrict__ ef,
              const int*   __restrict__ src_idx,
              const float* __restrict__ We,  const float* __restrict__ be,
              const float* __restrict__ Wa,  const float* __restrict__ ba,
              const float* __restrict__ wa,
              const float* __restrict__ Wo,  const float* __restrict__ bo,
              const float* __restrict__ Wn,  const float* __restrict__ bn,
              float* __restrict__ out)
{
    extern __shared__ char smc[];
    const int tid = threadIdx.x, lane = tid & 31, wid = tid >> 5;
    const int mrow = (wid & 3) * 32, ncol = (wid >> 2) * 32;

    float* sLog = (float*)(smc + OFF_LOG);
    float* sTau = (float*)(smc + OFF_TAU);
    float* sAmx = (float*)(smc + OFF_AMX);
    float* sV   = (float*)(smc + OFF_V);
    float* sBe  = (float*)(smc + OFF_BE);
    float* sBo  = (float*)(smc + OFF_BO);
    float* sBn  = (float*)(smc + OFF_BN);
    int*   sSrc = (int*)  (smc + OFF_SRC);

    // one-time staging: 3 weight matrices hi/lo (stride 72), biases, v, c
    for (int i = tid; i < 4096; i += 256) {
        const int n = i >> 6, k = i & 63;
        const float w1 = We[k * 64 + n];
        const float w2 = Wo[(NODE_IN + k) * 64 + n];
        const float w3 = Wn[(NODE_IN + k) * 64 + n];
        const __nv_bfloat16 h1 = __float2bfloat16(w1);
        const __nv_bfloat16 h2 = __float2bfloat16(w2);
        const __nv_bfloat16 h3 = __float2bfloat16(w3);
        ((__nv_bfloat16*)(smc + OFF_W1H))[n * 72 + k] = h1;
        ((__nv_bfloat16*)(smc + OFF_W1L))[n * 72 + k] = __float2bfloat16(w1 - __bfloat162float(h1));
        ((__nv_bfloat16*)(smc + OFF_W2H))[n * 72 + k] = h2;
        ((__nv_bfloat16*)(smc + OFF_W2L))[n * 72 + k] = __float2bfloat16(w2 - __bfloat162float(h2));
        ((__nv_bfloat16*)(smc + OFF_W3H))[n * 72 + k] = h3;
        ((__nv_bfloat16*)(smc + OFF_W3L))[n * 72 + k] = __float2bfloat16(w3 - __bfloat162float(h3));
    }
    // zero HN pad rows 8..15 (never written again)
    for (int i = tid; i < 288; i += 256) {
        ((uint32_t*)(smc + OFF_HNH + 1152))[i] = 0;
        ((uint32_t*)(smc + OFF_HNL + 1152))[i] = 0;
    }
    if (tid < 64) {
        sBe[tid] = be[tid]; sBo[tid] = bo[tid]; sBn[tid] = bn[tid];
        float sv = 0.f;
        #pragma unroll 8
        for (int k = 0; k < 64; k++) sv = fmaf(Wa[tid * 64 + k], wa[k], sv);
        sV[tid] = sv;
    }
    if (tid == 64) {
        float sc = 0.f;
        for (int k = 0; k < 64; k++) sc = fmaf(ba[k], wa[k], sc);
        *(float*)(smc + OFF_C) = sc;
    }
    __syncthreads();
    const float cval = *(const float*)(smc + OFF_C);

    const uint32_t eH  = smem_u32(smc + OFF_EH),  eL  = smem_u32(smc + OFF_EL);
    const uint32_t w1H = smem_u32(smc + OFF_W1H), w1L = smem_u32(smc + OFF_W1L);
    const uint32_t w2H = smem_u32(smc + OFF_W2H), w2L = smem_u32(smc + OFF_W2L);
    const uint32_t w3H = smem_u32(smc + OFF_W3H), w3L = smem_u32(smc + OFF_W3L);
    const uint32_t hnH = smem_u32(smc + OFF_HNH), hnL = smem_u32(smc + OFF_HNL);

    for (int tile = blockIdx.x; tile < NTILE; tile += gridDim.x) {
        __syncthreads();   // reuse guard (E, HN, sLog)

        // ---- stage E tile [128 x 64] -> hi/lo bf16 (b64 stores) + fused
        //      fp32 logit partials (shuffle-reduced over 16 lanes / row) ----
        const float4* eg = (const float4*)(ef + (size_t)tile * 8192);
        #pragma unroll
        for (int t = 0; t < 8; t++) {
            const int idx = tid + 256 * t;       // 0..2047
            const int r = idx >> 4, q = idx & 15;
            const float4 v = eg[idx];
            __nv_bfloat162 h0, l0, h1, l1;
            split2(v.x, v.y, h0, l0);
            split2(v.z, v.w, h1, l1);
            const size_t bo_ = (size_t)(r * 72 + 4 * q) * 2;
            *(uint2*)(smc + OFF_EH + bo_) = make_uint2(b2u(h0), b2u(h1));
            *(uint2*)(smc + OFF_EL + bo_) = make_uint2(b2u(l0), b2u(l1));
            float p = v.x * sV[4 * q] + v.y * sV[4 * q + 1]
                    + v.z * sV[4 * q + 2] + v.w * sV[4 * q + 3];
            p += __shfl_xor_sync(0xffffffffu, p, 1);
            p += __shfl_xor_sync(0xffffffffu, p, 2);
            p += __shfl_xor_sync(0xffffffffu, p, 4);
            p += __shfl_xor_sync(0xffffffffu, p, 8);
            if ((tid & 15) == 0) sLog[r] = p;
        }
        if (tid < 128) sSrc[tid] = src_idx[tile * 128 + tid];
        __syncthreads();

        // ---- sparsemax (warp 0, 8 threads) — overlaps with GEMM1 ----
        if (tid < 8) {
            float z[16], amax = -3.4e38f;
            #pragma unroll
            for (int d = 0; d < 16; d++) {
                float raw = sLog[tid * 16 + d] + cval;
                raw = (raw > 0.f) ? raw : 0.01f * raw;   // leaky_relu
                sLog[tid * 16 + d] = raw;                // for alpha in epi2
                z[d] = raw; amax = fmaxf(amax, z[d]);
            }
            #pragma unroll
            for (int d = 0; d < 16; d++) z[d] -= amax;
            #pragma unroll
            for (int kk2 = 2; kk2 <= 16; kk2 <<= 1)
                #pragma unroll
                for (int j = kk2 >> 1; j > 0; j >>= 1)
                    #pragma unroll
                    for (int i = 0; i < 16; i++) {
                        const int l = i ^ j;
                        if (l > i) {
                            const bool up = ((i & kk2) == 0);
                            const float a0 = z[i], b0 = z[l];
                            if (up ? (a0 > b0) : (a0 < b0)) { z[i] = b0; z[l] = a0; }
                        }
                    }
            float cs = 0.f, cssel = 0.f, kk = 1.f;
            #pragma unroll
            for (int j = 1; j <= 16; j++) {
                const float zz = z[16 - j];
                cs += zz;
                if (1.f + (float)j * zz > cs) { kk = (float)j; cssel = cs; }
            }
            sTau[tid] = (cssel - 1.f) / kk;
            sAmx[tid] = amax;
        }

        float acc[2][4][4];

        // ---- GEMM1: e_out_pre = E @ We^T ----
        #pragma unroll
        for (int a = 0; a < 2; a++)
            #pragma unroll
            for (int b = 0; b < 4; b++)
                #pragma unroll
                for (int c = 0; c < 4; c++) acc[a][b][c] = 0.f;
        gemm_x3<4, 72>(eH, eL, w1H, w1L, mrow, ncol, lane, acc);
        __syncthreads();   // all E reads complete (e_out aliases E)

        // ---- epilogue1: relu(+be) -> bf16 hi/lo back into E buffers ----
        #pragma unroll
        for (int mt = 0; mt < 2; mt++) {
            const int r0 = mrow + mt * 16 + (lane >> 2);
            #pragma unroll
            for (int nt = 0; nt < 4; nt++) {
                const int c = ncol + nt * 8 + (lane & 3) * 2;
                const float x0 = fmaxf(acc[mt][nt][0] + sBe[c],     0.f);
                const float x1 = fmaxf(acc[mt][nt][1] + sBe[c + 1], 0.f);
                const float x2 = fmaxf(acc[mt][nt][2] + sBe[c],     0.f);
                const float x3 = fmaxf(acc[mt][nt][3] + sBe[c + 1], 0.f);
                __nv_bfloat162 h0, l0, h1, l1;
                split2(x0, x1, h0, l0);
                split2(x2, x3, h1, l1);
                *(uint32_t*)(smc + OFF_EH + (size_t)(r0 * 72 + c) * 2) = b2u(h0);
                *(uint32_t*)(smc + OFF_EL + (size_t)(r0 * 72 + c) * 2) = b2u(l0);
                *(uint32_t*)(smc + OFF_EH + (size_t)((r0 + 8) * 72 + c) * 2) = b2u(h1);
                *(uint32_t*)(smc + OFF_EL + (size_t)((r0 + 8) * 72 + c) * 2) = b2u(l1);
            }
        }
        __syncthreads();

        // ---- GEMM2: m_pre = e_out @ Wo_bot^T ----
        #pragma unroll
        for (int a = 0; a < 2; a++)
            #pragma unroll
            for (int b = 0; b < 4; b++)
                #pragma unroll
                for (int c = 0; c < 4; c++) acc[a][b][c] = 0.f;
        gemm_x3<4, 72>(eH, eL, w2H, w2L, mrow, ncol, lane, acc);

        // ---- epilogue2: m = relu(m_pre + P[src] + bo); alpha-weighted sum
        //      -> HN as bf16 hi/lo (rows 0..7) ----
        #pragma unroll
        for (int mt = 0; mt < 2; mt++) {
            const int ln = (mrow >> 4) + mt;               // local node 0..7
            const int r0 = mrow + mt * 16 + (lane >> 2);
            const int r1 = r0 + 8;
            const int s0 = sSrc[r0], s1 = sSrc[r1];
            const float al0 = fmaxf(sLog[r0] - sAmx[ln] - sTau[ln], 0.f);
            const float al1 = fmaxf(sLog[r1] - sAmx[ln] - sTau[ln], 0.f);
            #pragma unroll
            for (int nt = 0; nt < 4; nt++) {
                const int c = ncol + nt * 8 + (lane & 3) * 2;
                const float2 p0 = *(const float2*)(g_P + (size_t)s0 * HID + c);
                const float2 p1 = *(const float2*)(g_P + (size_t)s1 * HID + c);
                const float m00 = fmaxf(acc[mt][nt][0] + p0.x + sBo[c],     0.f);
                const float m01 = fmaxf(acc[mt][nt][1] + p0.y + sBo[c + 1], 0.f);
                const float m10 = fmaxf(acc[mt][nt][2] + p1.x + sBo[c],     0.f);
                const float m11 = fmaxf(acc[mt][nt][3] + p1.y + sBo[c + 1], 0.f);
                float sx = m00 * al0 + m10 * al1;
                float sy = m01 * al0 + m11 * al1;
                sx += __shfl_xor_sync(0xffffffffu, sx, 4);
                sy += __shfl_xor_sync(0xffffffffu, sy, 4);
                sx += __shfl_xor_sync(0xffffffffu, sx, 8);
                sy += __shfl_xor_sync(0xffffffffu, sy, 8);
                sx += __shfl_xor_sync(0xffffffffu, sx, 16);
                sy += __shfl_xor_sync(0xffffffffu, sy, 16);
                if (lane < 4) {
                    __nv_bfloat162 hh, ll;
                    split2(sx, sy, hh, ll);
                    *(uint32_t*)(smc + OFF_HNH + (size_t)(ln * 72 + c) * 2) = b2u(hh);
                    *(uint32_t*)(smc + OFF_HNL + (size_t)(ln * 72 + c) * 2) = b2u(ll);
                }
            }
        }
        __syncthreads();

        // ---- GEMM3 (MMA, M=16 padded): out = relu(R + HN @ Wn_bot^T + bn)
        //      each warp owns 8 output cols ----
        {
            const int nc = wid * 8;
            float acc3[4] = {0.f, 0.f, 0.f, 0.f};
            uint32_t a3h[4][4], a3l[4][4], b3h[2][4], b3l[2][4];
            #pragma unroll
            for (int ks = 0; ks < 4; ks++) {
                const uint32_t off = (uint32_t)(((lane & 15) * 72 + ks * 16 + (lane >> 4) * 8) * 2);
                ldsm4(a3h[ks], hnH + off);
                ldsm4(a3l[ks], hnL + off);
            }
            #pragma unroll
            for (int g = 0; g < 2; g++) {
                const uint32_t off = (uint32_t)(((nc + (lane & 7)) * 72 + (lane >> 3) * 8 + g * 32) * 2);
                ldsm4(b3h[g], w3H + off);
                ldsm4(b3l[g], w3L + off);
            }
            #pragma unroll
            for (int ks = 0; ks < 4; ks++) {
                const int g = ks >> 1, pr = (ks & 1) * 2;
                const uint32_t bh0 = b3h[g][pr], bh1 = b3h[g][pr + 1];
                const uint32_t bl0 = b3l[g][pr], bl1 = b3l[g][pr + 1];
                mma_bf16(acc3, a3h[ks], bh0, bh1);
                mma_bf16(acc3, a3h[ks], bl0, bl1);
                mma_bf16(acc3, a3l[ks], bh0, bh1);
            }
            const int node = tile * 8 + (lane >> 2);
            const int col = nc + (lane & 3) * 2;
            const float2 r2 = *(const float2*)(g_R + (size_t)node * HID + col);
            const float o0 = acc3[0] + r2.x + sBn[col];
            const float o1 = acc3[1] + r2.y + sBn[col + 1];
            *(float2*)(out + (size_t)node * HID + col) =
                make_float2(fmaxf(o0, 0.f), fmaxf(o1, 0.f));
        }
    }
}

// ---------------------------------------------------------------------------
extern "C" void kernel_launch(void* const* d_in, const int* in_sizes, int n_in,
                              void* d_out, int out_size)
{
    const float* nf = (const float*)d_in[0];
    const float* ef = (const float*)d_in[1];
    const int*   si = (const int*)  d_in[2];
    const float* We = (const float*)d_in[3];
    const float* be = (const float*)d_in[4];
    const float* Wa = (const float*)d_in[5];
    const float* ba = (const float*)d_in[6];
    const float* wa = (const float*)d_in[7];
    const float* Wo = (const float*)d_in[8];
    const float* bo = (const float*)d_in[9];
    const float* Wn = (const float*)d_in[10];
    const float* bn = (const float*)d_in[11];
    float* out = (float*)d_out;

    cudaFuncSetAttribute(k_projT,  cudaFuncAttributeMaxDynamicSharedMemorySize, PJ_SMEM);
    cudaFuncSetAttribute(k_fusedT, cudaFuncAttributeMaxDynamicSharedMemorySize, FS_SMEM);

    k_projT<<<PJ_BLOCKS, 256, PJ_SMEM>>>(nf, Wo, Wn);
    k_fusedT<<<296, 256, FS_SMEM>>>(ef, si, We, be, Wa, ba, wa, Wo, bo, Wn, bn, out);
}